// round 5
// baseline (speedup 1.0000x reference)
#include <cuda_runtime.h>
#include <math.h>

// Problem constants: N=2, C=64, H=W=128
#define PHW 16384

// ---------------- scratch (static device globals; no allocation) ----------------
__device__ float g_xd[2*64*PHW];       // upsample+conv+pad output (2,64,128,128)
__device__ float g_xl_nhwc[2*PHW*64];  // xl in NHWC for fast bilinear gathers
__device__ float g_xr_nhwc[2*PHW*64];
__device__ float g_ol[2*27*PHW];       // offset-conv output (raw; sigmoid applied in sampler)
__device__ float g_col[2*576*PHW];     // im2col buffer: [n][k*64+c][p], samp*mask
__device__ float g_wt[576*64];         // deform weights transposed: [q=k*64+c][o]
__device__ float g_xl2[2*64*PHW];      // deformed xl
__device__ float g_xr2[2*64*PHW];      // deformed xr
__device__ float g_t1[2*64*PHW];
__device__ float g_t2[2*64*PHW];
__device__ float g_t3[2*64*PHW];

// ---------------- NCHW(64ch) -> NHWC transpose ----------------
__global__ void __launch_bounds__(256) k_tr(const float* __restrict__ in, float* __restrict__ out) {
    __shared__ float sm[64][65];
    int n = blockIdx.y;
    int p0 = blockIdx.x * 64;
    int t = threadIdx.x;
    for (int idx = t; idx < 64*64; idx += 256) {
        int c = idx >> 6, px = idx & 63;
        sm[c][px] = in[(n*64 + c)*PHW + p0 + px];
    }
    __syncthreads();
    for (int idx = t; idx < 64*64; idx += 256) {
        int px = idx >> 6, c = idx & 63;
        out[(n*PHW + p0 + px)*64 + c] = sm[c][px];
    }
}

// ---------------- nearest-up 2x + 2x2 conv (pad 0) + pad to 128x128 ----------------
// grid (8,8,4): z = n*2 + coChunk ; block 256 threads, 1 pixel/thread, 32 co/thread
__global__ void __launch_bounds__(256) k_upconv(const float* __restrict__ xin,
                                                const float* __restrict__ w,
                                                const float* __restrict__ bias) {
    __shared__ float in_sh[17*17];
    __shared__ float ws[32*4];
    int t = threadIdx.x;
    int n = blockIdx.z >> 1;
    int coBase = (blockIdx.z & 1) * 32;
    int x0b = blockIdx.x * 16, y0b = blockIdx.y * 16;
    int xl = t & 15, yl = t >> 4;
    float acc[32];
    #pragma unroll
    for (int i = 0; i < 32; i++) acc[i] = 0.f;
    #pragma unroll 1
    for (int ci = 0; ci < 128; ci++) {
        const float* plane = xin + (n*128 + ci)*4096;  // (64,64) plane
        for (int idx = t; idx < 289; idx += 256) {
            int r = idx / 17, cc = idx - r*17;
            int gy = y0b + r; if (gy > 127) gy = 127;
            int gx = x0b + cc; if (gx > 127) gx = 127;
            in_sh[idx] = plane[(gy >> 1)*64 + (gx >> 1)];   // nearest upsample on the fly
        }
        if (t < 128) {
            int co = t >> 2, k = t & 3;
            ws[t] = w[((coBase + co)*128 + ci)*4 + k];
        }
        __syncthreads();
        float a[4];
        #pragma unroll
        for (int dy = 0; dy < 2; dy++)
        #pragma unroll
        for (int dx = 0; dx < 2; dx++)
            a[dy*2+dx] = in_sh[(yl+dy)*17 + xl + dx];
        #pragma unroll
        for (int co = 0; co < 32; co++) {
            #pragma unroll
            for (int k = 0; k < 4; k++)
                acc[co] += ws[co*4 + k] * a[k];
        }
        __syncthreads();
    }
    int y = y0b + yl, x = x0b + xl;
    #pragma unroll
    for (int co = 0; co < 32; co++) {
        int cog = coBase + co;
        float v = (y < 127 && x < 127) ? (acc[co] + bias[cog]) : 0.f;  // pad region = 0
        g_xd[((n*64 + cog)*128 + y)*128 + x] = v;
    }
}

// ---------------- generic 3x3 conv, pad 1, up to 3 concatenated 64-ch sources ----------------
// grid (8,8, 2*nChunks); block 256; 1 pixel/thread, CO output channels/thread
template<int CIN, int CO, bool RELU, bool RES>
__global__ void __launch_bounds__(256) k_conv3x3(
    const float* __restrict__ s0, const float* __restrict__ s1, const float* __restrict__ s2,
    const float* __restrict__ w, const float* __restrict__ bias,
    float* __restrict__ out, const float* __restrict__ res,
    int coutTotal, int nChunks)
{
    __shared__ float in_sh[18*18];
    __shared__ float ws[CO*9];
    int t = threadIdx.x;
    int n = blockIdx.z / nChunks;
    int coBase = (blockIdx.z % nChunks) * CO;
    int x0b = blockIdx.x * 16, y0b = blockIdx.y * 16;
    int xl = t & 15, yl = t >> 4;
    float acc[CO];
    #pragma unroll
    for (int i = 0; i < CO; i++) acc[i] = 0.f;
    #pragma unroll 1
    for (int ci = 0; ci < CIN; ci++) {
        const float* src;
        if (CIN == 64) src = s0;
        else src = (ci < 64) ? s0 : ((ci < 128) ? s1 : s2);
        int c = ci & 63;
        const float* plane = src + (n*64 + c)*PHW;
        for (int idx = t; idx < 324; idx += 256) {
            int r = idx / 18, cc = idx - r*18;
            int gy = y0b + r - 1, gx = x0b + cc - 1;
            float v = 0.f;
            if (gy >= 0 && gy < 128 && gx >= 0 && gx < 128) v = plane[gy*128 + gx];
            in_sh[idx] = v;
        }
        for (int idx = t; idx < CO*9; idx += 256) {
            int co = idx / 9, k = idx - co*9;
            ws[idx] = w[((coBase + co)*CIN + ci)*9 + k];
        }
        __syncthreads();
        float a[9];
        #pragma unroll
        for (int dy = 0; dy < 3; dy++)
        #pragma unroll
        for (int dx = 0; dx < 3; dx++)
            a[dy*3+dx] = in_sh[(yl+dy)*18 + xl + dx];
        #pragma unroll
        for (int co = 0; co < CO; co++) {
            #pragma unroll
            for (int k = 0; k < 9; k++)
                acc[co] += ws[co*9 + k] * a[k];
        }
        __syncthreads();
    }
    int y = y0b + yl, x = x0b + xl;
    #pragma unroll
    for (int co = 0; co < CO; co++) {
        int cog = coBase + co;
        if (cog < coutTotal) {
            int oidx = ((n*coutTotal + cog)*128 + y)*128 + x;
            float v = acc[co] + bias[cog];
            if (RES) v += res[oidx];
            if (RELU) v = fmaxf(v, 0.f);
            out[oidx] = v;
        }
    }
}

// ---------------- deform weight transpose: g_wt[q=k*64+c][o] = dw[o][c][k] ----------------
__global__ void __launch_bounds__(256) k_wt(const float* __restrict__ dw) {
    int i = blockIdx.x*256 + threadIdx.x;
    if (i < 576*64) {
        int q = i >> 6, o = i & 63;
        int c = q & 63, k = q >> 6;
        g_wt[q*64 + o] = dw[(o*64 + c)*9 + k];
    }
}

// ---------------- bilinear sampling: build g_col[n][k*64+c][p] = samp * sigmoid(mask) ----------------
// one thread per (n,k,h,w); 64 channels via float4 gathers from NHWC source
__global__ void __launch_bounds__(256) k_sample(const float* __restrict__ xnhwc,
                                                const float* __restrict__ ol) {
    int id = blockIdx.x*256 + threadIdx.x;      // < 2*9*16384
    int p = id & 16383;
    int v = id >> 14;                            // n*9 + k
    int k = v % 9;
    int n = v / 9;
    int h = p >> 7, wcol = p & 127;
    const float* olb = ol + n*27*PHW;
    float dy = olb[(2*k)*PHW + p];
    float dx = olb[(2*k + 1)*PHW + p];
    float m  = 1.f / (1.f + expf(-olb[(18 + k)*PHW + p]));
    float py = (float)(h + k/3 - 1) + dy;
    float px = (float)(wcol + k%3 - 1) + dx;
    float y0 = floorf(py), x0 = floorf(px);
    float wy = py - y0, wx = px - x0;
    int iy0 = (int)y0, ix0 = (int)x0;
    int iy1 = iy0 + 1, ix1 = ix0 + 1;
    float vy0 = (iy0 >= 0 && iy0 < 128) ? 1.f : 0.f;
    float vy1 = (iy1 >= 0 && iy1 < 128) ? 1.f : 0.f;
    float vx0 = (ix0 >= 0 && ix0 < 128) ? 1.f : 0.f;
    float vx1 = (ix1 >= 0 && ix1 < 128) ? 1.f : 0.f;
    float c00 = (1.f-wy)*(1.f-wx)*m*vy0*vx0;
    float c01 = (1.f-wy)*wx*m*vy0*vx1;
    float c10 = wy*(1.f-wx)*m*vy1*vx0;
    float c11 = wy*wx*m*vy1*vx1;
    int cy0 = min(max(iy0,0),127), cy1 = min(max(iy1,0),127);
    int cx0 = min(max(ix0,0),127), cx1 = min(max(ix1,0),127);
    const float4* b00 = (const float4*)(xnhwc + ((n*128 + cy0)*128 + cx0)*64);
    const float4* b01 = (const float4*)(xnhwc + ((n*128 + cy0)*128 + cx1)*64);
    const float4* b10 = (const float4*)(xnhwc + ((n*128 + cy1)*128 + cx0)*64);
    const float4* b11 = (const float4*)(xnhwc + ((n*128 + cy1)*128 + cx1)*64);
    float* colb = g_col + (n*576 + k*64)*PHW + p;
    #pragma unroll
    for (int j = 0; j < 16; j++) {
        float4 a = b00[j], b = b01[j], c = b10[j], d = b11[j];
        colb[(4*j + 0)*PHW] = a.x*c00 + b.x*c01 + c.x*c10 + d.x*c11;
        colb[(4*j + 1)*PHW] = a.y*c00 + b.y*c01 + c.y*c10 + d.y*c11;
        colb[(4*j + 2)*PHW] = a.z*c00 + b.z*c01 + c.z*c10 + d.z*c11;
        colb[(4*j + 3)*PHW] = a.w*c00 + b.w*c01 + c.w*c10 + d.w*c11;
    }
}

// ---------------- deform matmul: out[n][o][p] = sum_q g_col[n][q][p] * g_wt[q][o] + b ----------------
// grid (8,8,4): z = n*2 + coChunk ; block 256; 1 pixel x 32 co per thread
__global__ void __launch_bounds__(256) k_dmatmul(const float* __restrict__ bias,
                                                 float* __restrict__ out) {
    __shared__ float ws[8*32];
    int t = threadIdx.x;
    int n = blockIdx.z >> 1;
    int coBase = (blockIdx.z & 1) * 32;
    int x0b = blockIdx.x*16, y0b = blockIdx.y*16;
    int xl = t & 15, yl = t >> 4;
    int p0 = (y0b + yl)*128 + x0b + xl;
    float acc[32];
    #pragma unroll
    for (int i = 0; i < 32; i++) acc[i] = 0.f;
    #pragma unroll 1
    for (int q0 = 0; q0 < 576; q0 += 8) {
        ws[t] = g_wt[(q0 + (t >> 5))*64 + coBase + (t & 31)];
        float v0[8];
        #pragma unroll
        for (int qq = 0; qq < 8; qq++) {
            const float* colp = g_col + (n*576 + q0 + qq)*PHW;
            v0[qq] = colp[p0];
        }
        __syncthreads();
        #pragma unroll
        for (int qq = 0; qq < 8; qq++)
        #pragma unroll
        for (int co = 0; co < 32; co++)
            acc[co] += ws[qq*32 + co] * v0[qq];
        __syncthreads();
    }
    #pragma unroll
    for (int co = 0; co < 32; co++) {
        int cog = coBase + co;
        out[(n*64 + cog)*PHW + p0] = acc[co] + bias[cog];
    }
}

// ---------------- launch ----------------
extern "C" void kernel_launch(void* const* d_in, const int* in_sizes, int n_in,
                              void* d_out, int out_size) {
    const float* xd     = (const float*)d_in[0];
    const float* xl     = (const float*)d_in[1];
    const float* xr     = (const float*)d_in[2];
    const float* up_w   = (const float*)d_in[3];
    const float* up_b   = (const float*)d_in[4];
    const float* offl_w = (const float*)d_in[5];
    const float* offl_b = (const float*)d_in[6];
    const float* dl_w   = (const float*)d_in[7];
    const float* dl_b   = (const float*)d_in[8];
    const float* offr_w = (const float*)d_in[9];
    const float* offr_b = (const float*)d_in[10];
    const float* dr_w   = (const float*)d_in[11];
    const float* dr_b   = (const float*)d_in[12];
    const float* cv_w   = (const float*)d_in[13];
    const float* cv_b   = (const float*)d_in[14];
    const float* rb1_w1 = (const float*)d_in[15];
    const float* rb1_w2 = (const float*)d_in[16];
    const float* rb2_w1 = (const float*)d_in[17];
    const float* rb2_w2 = (const float*)d_in[18];
    const float* rb1_b1 = (const float*)d_in[19];
    const float* rb1_b2 = (const float*)d_in[20];
    const float* rb2_b1 = (const float*)d_in[21];
    const float* rb2_b2 = (const float*)d_in[22];
    float* outp = (float*)d_out;

    // No static caching (harness forbids call-count-dependent behavior).
    // cudaGetSymbolAddress is not a stream op: capture-safe, identical every call.
    float *p_xd, *p_xlN, *p_xrN, *p_ol, *p_xl2, *p_xr2, *p_t1, *p_t2, *p_t3;
    cudaGetSymbolAddress((void**)&p_xd,  g_xd);
    cudaGetSymbolAddress((void**)&p_xlN, g_xl_nhwc);
    cudaGetSymbolAddress((void**)&p_xrN, g_xr_nhwc);
    cudaGetSymbolAddress((void**)&p_ol,  g_ol);
    cudaGetSymbolAddress((void**)&p_xl2, g_xl2);
    cudaGetSymbolAddress((void**)&p_xr2, g_xr2);
    cudaGetSymbolAddress((void**)&p_t1,  g_t1);
    cudaGetSymbolAddress((void**)&p_t2,  g_t2);
    cudaGetSymbolAddress((void**)&p_t3,  g_t3);

    // NHWC copies of the bilinear-sample sources (original xl, xr)
    k_tr<<<dim3(256,2),256>>>(xl, p_xlN);
    k_tr<<<dim3(256,2),256>>>(xr, p_xrN);

    // upsample + 2x2 conv + pad
    k_upconv<<<dim3(8,8,4),256>>>(xd, up_w, up_b);

    // left offsets + deform(xl)
    k_conv3x3<192,27,false,false><<<dim3(8,8,2),256>>>(xl, xr, p_xd, offl_w, offl_b, p_ol, nullptr, 27, 1);
    k_wt<<<144,256>>>(dl_w);
    k_sample<<<1152,256>>>(p_xlN, p_ol);
    k_dmatmul<<<dim3(8,8,4),256>>>(dl_b, p_xl2);

    // right offsets (using new xl) + deform(xr)
    k_conv3x3<192,27,false,false><<<dim3(8,8,2),256>>>(p_xl2, xr, p_xd, offr_w, offr_b, p_ol, nullptr, 27, 1);
    k_wt<<<144,256>>>(dr_w);
    k_sample<<<1152,256>>>(p_xrN, p_ol);
    k_dmatmul<<<dim3(8,8,4),256>>>(dr_b, p_xr2);

    // fuse conv (relu)
    k_conv3x3<192,32,true,false><<<dim3(8,8,4),256>>>(p_xl2, p_xr2, p_xd, cv_w, cv_b, p_t1, nullptr, 64, 2);

    // res block 1
    k_conv3x3<64,32,true,false ><<<dim3(8,8,4),256>>>(p_t1, nullptr, nullptr, rb1_w1, rb1_b1, p_t2, nullptr, 64, 2);
    k_conv3x3<64,32,false,true ><<<dim3(8,8,4),256>>>(p_t2, nullptr, nullptr, rb1_w2, rb1_b2, p_t3, p_t1, 64, 2);

    // res block 2 -> final output
    k_conv3x3<64,32,true,false ><<<dim3(8,8,4),256>>>(p_t3, nullptr, nullptr, rb2_w1, rb2_b1, p_t2, nullptr, 64, 2);
    k_conv3x3<64,32,false,true ><<<dim3(8,8,4),256>>>(p_t2, nullptr, nullptr, rb2_w2, rb2_b2, outp, p_t3, 64, 2);
}

// round 9
// speedup vs baseline: 1.3639x; 1.3639x over previous
#include <cuda_runtime.h>
#include <math.h>

// Problem constants: N=2, C=64, H=W=128
#define PHW 16384

// ---------------- scratch (static device globals; no allocation) ----------------
__device__ float g_xd[2*64*PHW];       // upsample+conv+pad output (2,64,128,128)
__device__ float g_xl_nhwc[2*PHW*64];  // xl in NHWC for fast bilinear gathers
__device__ float g_xr_nhwc[2*PHW*64];
__device__ float g_ol[2*27*PHW];       // offset-conv output (raw; sigmoid applied in sampler)
__device__ float g_col[2*576*PHW];     // im2col buffer: [n][k*64+c][p], samp*mask
__device__ float g_wt[576*64];         // deform weights transposed: [q=k*64+c][o]
__device__ float g_xl2[2*64*PHW];      // deformed xl
__device__ float g_xr2[2*64*PHW];      // deformed xr
__device__ float g_t1[2*64*PHW];
__device__ float g_t2[2*64*PHW];
__device__ float g_t3[2*64*PHW];

// ---------------- NCHW(64ch) -> NHWC transpose ----------------
__global__ void __launch_bounds__(256) k_tr(const float* __restrict__ in, float* __restrict__ out) {
    __shared__ float sm[64][65];
    int n = blockIdx.y;
    int p0 = blockIdx.x * 64;
    int t = threadIdx.x;
    for (int idx = t; idx < 64*64; idx += 256) {
        int c = idx >> 6, px = idx & 63;
        sm[c][px] = in[(n*64 + c)*PHW + p0 + px];
    }
    __syncthreads();
    for (int idx = t; idx < 64*64; idx += 256) {
        int px = idx >> 6, c = idx & 63;
        out[(n*PHW + p0 + px)*64 + c] = sm[c][px];
    }
}

// ---------------- nearest-up 2x + 2x2 conv (pad 0) + pad to 128x128 ----------------
// grid (8,8,4): z = n*2 + coChunk ; block 256, 1 px/thread, 32 co/thread, 8-ch stages
__global__ void __launch_bounds__(256) k_upconv(const float* __restrict__ xin,
                                                const float* __restrict__ w,
                                                const float* __restrict__ bias) {
    __shared__ float in_sh[8][289];
    __shared__ float ws[8][128];
    int t = threadIdx.x;
    int n = blockIdx.z >> 1;
    int coBase = (blockIdx.z & 1) * 32;
    int x0b = blockIdx.x * 16, y0b = blockIdx.y * 16;
    int xl = t & 15, yl = t >> 4;
    float acc[32];
    #pragma unroll
    for (int i = 0; i < 32; i++) acc[i] = 0.f;
    #pragma unroll 1
    for (int c0 = 0; c0 < 128; c0 += 8) {
        for (int idx = t; idx < 8*289; idx += 256) {
            int cc = idx / 289, rem = idx - cc*289;
            const float* plane = xin + (n*128 + c0 + cc)*4096;  // (64,64) plane
            int r = rem / 17, col = rem - r*17;
            int gy = y0b + r; if (gy > 127) gy = 127;
            int gx = x0b + col; if (gx > 127) gx = 127;
            in_sh[cc][rem] = plane[(gy >> 1)*64 + (gx >> 1)];   // nearest upsample on the fly
        }
        for (int idx = t; idx < 8*128; idx += 256) {
            int cc = idx >> 7, rem = idx & 127;
            int co = rem >> 2, k = rem & 3;
            ws[cc][rem] = w[((coBase + co)*128 + c0 + cc)*4 + k];
        }
        __syncthreads();
        #pragma unroll 1
        for (int cc = 0; cc < 8; cc++) {
            float a[4];
            #pragma unroll
            for (int dy = 0; dy < 2; dy++)
            #pragma unroll
            for (int dx = 0; dx < 2; dx++)
                a[dy*2+dx] = in_sh[cc][(yl+dy)*17 + xl + dx];
            #pragma unroll
            for (int co = 0; co < 32; co++) {
                #pragma unroll
                for (int k = 0; k < 4; k++)
                    acc[co] += ws[cc][co*4 + k] * a[k];
            }
        }
        __syncthreads();
    }
    int y = y0b + yl, x = x0b + xl;
    #pragma unroll
    for (int co = 0; co < 32; co++) {
        int cog = coBase + co;
        float v = (y < 127 && x < 127) ? (acc[co] + bias[cog]) : 0.f;  // pad region = 0
        g_xd[((n*64 + cog)*128 + y)*128 + x] = v;
    }
}

// ---------------- generic 3x3 conv, pad 1, up to 3 concatenated 64-ch sources ----------------
// grid (8,8, nChunks*2); block 256; 1 px/thread, CO out-ch/thread, 8-input-ch smem stages
template<int CIN, int CO, bool RELU, bool RES>
__global__ void __launch_bounds__(256) k_conv3x3(
    const float* __restrict__ s0, const float* __restrict__ s1, const float* __restrict__ s2,
    const float* __restrict__ w, const float* __restrict__ bias,
    float* __restrict__ out, const float* __restrict__ res,
    int coutTotal, int nChunks)
{
    __shared__ float in_sh[8][324];
    __shared__ float ws[8][CO*9];
    int t = threadIdx.x;
    int n = blockIdx.z / nChunks;
    int coBase = (blockIdx.z % nChunks) * CO;
    int x0b = blockIdx.x * 16, y0b = blockIdx.y * 16;
    int xl = t & 15, yl = t >> 4;
    float acc[CO];
    #pragma unroll
    for (int i = 0; i < CO; i++) acc[i] = 0.f;
    #pragma unroll 1
    for (int c0 = 0; c0 < CIN; c0 += 8) {
        // stage 8 input planes (all 8 channels' LDGs in flight before the barrier)
        for (int idx = t; idx < 8*324; idx += 256) {
            int cc = idx / 324, rem = idx - cc*324;
            int ci = c0 + cc;
            const float* src;
            if (CIN == 64) src = s0;
            else src = (ci < 64) ? s0 : ((ci < 128) ? s1 : s2);
            const float* plane = src + (n*64 + (ci & 63))*PHW;
            int r = rem / 18, col = rem - r*18;
            int gy = y0b + r - 1, gx = x0b + col - 1;
            float v = 0.f;
            if (gy >= 0 && gy < 128 && gx >= 0 && gx < 128) v = plane[gy*128 + gx];
            in_sh[cc][rem] = v;
        }
        for (int idx = t; idx < 8*CO*9; idx += 256) {
            int cc = idx / (CO*9), rem = idx - cc*(CO*9);
            int co = rem / 9, k = rem - co*9;
            ws[cc][rem] = w[((coBase + co)*CIN + c0 + cc)*9 + k];
        }
        __syncthreads();
        #pragma unroll 1
        for (int cc = 0; cc < 8; cc++) {
            float a[9];
            #pragma unroll
            for (int dy = 0; dy < 3; dy++)
            #pragma unroll
            for (int dx = 0; dx < 3; dx++)
                a[dy*3+dx] = in_sh[cc][(yl+dy)*18 + xl + dx];
            #pragma unroll
            for (int co = 0; co < CO; co++) {
                #pragma unroll
                for (int k = 0; k < 9; k++)
                    acc[co] += ws[cc][co*9 + k] * a[k];
            }
        }
        __syncthreads();
    }
    int y = y0b + yl, x = x0b + xl;
    #pragma unroll
    for (int co = 0; co < CO; co++) {
        int cog = coBase + co;
        if (cog < coutTotal) {
            int oidx = ((n*coutTotal + cog)*128 + y)*128 + x;
            float v = acc[co] + bias[cog];
            if (RES) v += res[oidx];
            if (RELU) v = fmaxf(v, 0.f);
            out[oidx] = v;
        }
    }
}

// ---------------- deform weight transpose: g_wt[q=k*64+c][o] = dw[o][c][k] ----------------
__global__ void __launch_bounds__(256) k_wt(const float* __restrict__ dw) {
    int i = blockIdx.x*256 + threadIdx.x;
    if (i < 576*64) {
        int q = i >> 6, o = i & 63;
        int c = q & 63, k = q >> 6;
        g_wt[q*64 + o] = dw[(o*64 + c)*9 + k];
    }
}

// ---------------- bilinear sampling: build g_col[n][k*64+c][p] = samp * sigmoid(mask) ----------------
// one thread per (n,k,h,w); 64 channels via float4 gathers from NHWC source
__global__ void __launch_bounds__(256) k_sample(const float* __restrict__ xnhwc,
                                                const float* __restrict__ ol) {
    int id = blockIdx.x*256 + threadIdx.x;      // < 2*9*16384
    int p = id & 16383;
    int v = id >> 14;                            // n*9 + k
    int k = v % 9;
    int n = v / 9;
    int h = p >> 7, wcol = p & 127;
    const float* olb = ol + n*27*PHW;
    float dy = olb[(2*k)*PHW + p];
    float dx = olb[(2*k + 1)*PHW + p];
    float m  = 1.f / (1.f + expf(-olb[(18 + k)*PHW + p]));
    float py = (float)(h + k/3 - 1) + dy;
    float px = (float)(wcol + k%3 - 1) + dx;
    float y0 = floorf(py), x0 = floorf(px);
    float wy = py - y0, wx = px - x0;
    int iy0 = (int)y0, ix0 = (int)x0;
    int iy1 = iy0 + 1, ix1 = ix0 + 1;
    float vy0 = (iy0 >= 0 && iy0 < 128) ? 1.f : 0.f;
    float vy1 = (iy1 >= 0 && iy1 < 128) ? 1.f : 0.f;
    float vx0 = (ix0 >= 0 && ix0 < 128) ? 1.f : 0.f;
    float vx1 = (ix1 >= 0 && ix1 < 128) ? 1.f : 0.f;
    float c00 = (1.f-wy)*(1.f-wx)*m*vy0*vx0;
    float c01 = (1.f-wy)*wx*m*vy0*vx1;
    float c10 = wy*(1.f-wx)*m*vy1*vx0;
    float c11 = wy*wx*m*vy1*vx1;
    int cy0 = min(max(iy0,0),127), cy1 = min(max(iy1,0),127);
    int cx0 = min(max(ix0,0),127), cx1 = min(max(ix1,0),127);
    const float4* b00 = (const float4*)(xnhwc + ((n*128 + cy0)*128 + cx0)*64);
    const float4* b01 = (const float4*)(xnhwc + ((n*128 + cy0)*128 + cx1)*64);
    const float4* b10 = (const float4*)(xnhwc + ((n*128 + cy1)*128 + cx0)*64);
    const float4* b11 = (const float4*)(xnhwc + ((n*128 + cy1)*128 + cx1)*64);
    float* colb = g_col + (n*576 + k*64)*PHW + p;
    #pragma unroll
    for (int j = 0; j < 16; j++) {
        float4 a = b00[j], b = b01[j], c = b10[j], d = b11[j];
        colb[(4*j + 0)*PHW] = a.x*c00 + b.x*c01 + c.x*c10 + d.x*c11;
        colb[(4*j + 1)*PHW] = a.y*c00 + b.y*c01 + c.y*c10 + d.y*c11;
        colb[(4*j + 2)*PHW] = a.z*c00 + b.z*c01 + c.z*c10 + d.z*c11;
        colb[(4*j + 3)*PHW] = a.w*c00 + b.w*c01 + c.w*c10 + d.w*c11;
    }
}

// ---------------- deform matmul: out[n][o][p] = sum_q g_col[n][q][p] * g_wt[q][o] + b ----------------
// grid (8,8,4): z = n*2 + coChunk ; block 256; 1 px x 32 co per thread; 16-q stages
__global__ void __launch_bounds__(256) k_dmatmul(const float* __restrict__ bias,
                                                 float* __restrict__ out) {
    __shared__ float ws[16*32];
    int t = threadIdx.x;
    int n = blockIdx.z >> 1;
    int coBase = (blockIdx.z & 1) * 32;
    int x0b = blockIdx.x*16, y0b = blockIdx.y*16;
    int xl = t & 15, yl = t >> 4;
    int p0 = (y0b + yl)*128 + x0b + xl;
    float acc[32];
    #pragma unroll
    for (int i = 0; i < 32; i++) acc[i] = 0.f;
    #pragma unroll 1
    for (int q0 = 0; q0 < 576; q0 += 16) {
        ws[t]       = g_wt[(q0 +      (t >> 5))*64 + coBase + (t & 31)];
        ws[t + 256] = g_wt[(q0 + 8 +  (t >> 5))*64 + coBase + (t & 31)];
        float v0[16];
        #pragma unroll
        for (int qq = 0; qq < 16; qq++) {
            const float* colp = g_col + (n*576 + q0 + qq)*PHW;
            v0[qq] = colp[p0];
        }
        __syncthreads();
        #pragma unroll
        for (int qq = 0; qq < 16; qq++)
        #pragma unroll
        for (int co = 0; co < 32; co++)
            acc[co] += ws[qq*32 + co] * v0[qq];
        __syncthreads();
    }
    #pragma unroll
    for (int co = 0; co < 32; co++) {
        int cog = coBase + co;
        out[(n*64 + cog)*PHW + p0] = acc[co] + bias[cog];
    }
}

// ---------------- launch ----------------
extern "C" void kernel_launch(void* const* d_in, const int* in_sizes, int n_in,
                              void* d_out, int out_size) {
    const float* xd     = (const float*)d_in[0];
    const float* xl     = (const float*)d_in[1];
    const float* xr     = (const float*)d_in[2];
    const float* up_w   = (const float*)d_in[3];
    const float* up_b   = (const float*)d_in[4];
    const float* offl_w = (const float*)d_in[5];
    const float* offl_b = (const float*)d_in[6];
    const float* dl_w   = (const float*)d_in[7];
    const float* dl_b   = (const float*)d_in[8];
    const float* offr_w = (const float*)d_in[9];
    const float* offr_b = (const float*)d_in[10];
    const float* dr_w   = (const float*)d_in[11];
    const float* dr_b   = (const float*)d_in[12];
    const float* cv_w   = (const float*)d_in[13];
    const float* cv_b   = (const float*)d_in[14];
    const float* rb1_w1 = (const float*)d_in[15];
    const float* rb1_w2 = (const float*)d_in[16];
    const float* rb2_w1 = (const float*)d_in[17];
    const float* rb2_w2 = (const float*)d_in[18];
    const float* rb1_b1 = (const float*)d_in[19];
    const float* rb1_b2 = (const float*)d_in[20];
    const float* rb2_b1 = (const float*)d_in[21];
    const float* rb2_b2 = (const float*)d_in[22];
    float* outp = (float*)d_out;

    // No static caching (harness forbids call-count-dependent behavior).
    // cudaGetSymbolAddress is not a stream op: capture-safe, identical every call.
    float *p_xd, *p_xlN, *p_xrN, *p_ol, *p_xl2, *p_xr2, *p_t1, *p_t2, *p_t3;
    cudaGetSymbolAddress((void**)&p_xd,  g_xd);
    cudaGetSymbolAddress((void**)&p_xlN, g_xl_nhwc);
    cudaGetSymbolAddress((void**)&p_xrN, g_xr_nhwc);
    cudaGetSymbolAddress((void**)&p_ol,  g_ol);
    cudaGetSymbolAddress((void**)&p_xl2, g_xl2);
    cudaGetSymbolAddress((void**)&p_xr2, g_xr2);
    cudaGetSymbolAddress((void**)&p_t1,  g_t1);
    cudaGetSymbolAddress((void**)&p_t2,  g_t2);
    cudaGetSymbolAddress((void**)&p_t3,  g_t3);

    // NHWC copies of the bilinear-sample sources (original xl, xr)
    k_tr<<<dim3(256,2),256>>>(xl, p_xlN);
    k_tr<<<dim3(256,2),256>>>(xr, p_xrN);

    // upsample + 2x2 conv + pad
    k_upconv<<<dim3(8,8,4),256>>>(xd, up_w, up_b);

    // left offsets + deform(xl)   (offset conv: CO=14 chunks -> 256 blocks)
    k_conv3x3<192,14,false,false><<<dim3(8,8,4),256>>>(xl, xr, p_xd, offl_w, offl_b, p_ol, nullptr, 27, 2);
    k_wt<<<144,256>>>(dl_w);
    k_sample<<<1152,256>>>(p_xlN, p_ol);
    k_dmatmul<<<dim3(8,8,4),256>>>(dl_b, p_xl2);

    // right offsets (using new xl) + deform(xr)
    k_conv3x3<192,14,false,false><<<dim3(8,8,4),256>>>(p_xl2, xr, p_xd, offr_w, offr_b, p_ol, nullptr, 27, 2);
    k_wt<<<144,256>>>(dr_w);
    k_sample<<<1152,256>>>(p_xrN, p_ol);
    k_dmatmul<<<dim3(8,8,4),256>>>(dr_b, p_xr2);

    // fuse conv (relu)
    k_conv3x3<192,32,true,false><<<dim3(8,8,4),256>>>(p_xl2, p_xr2, p_xd, cv_w, cv_b, p_t1, nullptr, 64, 2);

    // res block 1
    k_conv3x3<64,32,true,false ><<<dim3(8,8,4),256>>>(p_t1, nullptr, nullptr, rb1_w1, rb1_b1, p_t2, nullptr, 64, 2);
    k_conv3x3<64,32,false,true ><<<dim3(8,8,4),256>>>(p_t2, nullptr, nullptr, rb1_w2, rb1_b2, p_t3, p_t1, 64, 2);

    // res block 2 -> final output
    k_conv3x3<64,32,true,false ><<<dim3(8,8,4),256>>>(p_t3, nullptr, nullptr, rb2_w1, rb2_b1, p_t2, nullptr, 64, 2);
    k_conv3x3<64,32,false,true ><<<dim3(8,8,4),256>>>(p_t2, nullptr, nullptr, rb2_w2, rb2_b2, outp, p_t3, 64, 2);
}